// round 14
// baseline (speedup 1.0000x reference)
#include <cuda_runtime.h>
#include <math.h>

#define Bb 32
#define Tt 128
#define Ll 512
#define Dd 256
#define VOC 32000

#define FFMA2(acc, a, b) asm("fma.rn.f32x2 %0, %1, %2, %0;" : "+l"(acc) : "l"(a), "l"(b))

// ---------------- scratch ----------------
__device__ float g_x[Tt*Bb*Dd];             // [t*B+b][d]
__device__ float g_gx[2][Tt*Bb*768];        // [dir][t*B+b][gate*256+d]
__device__ float g_hbuf[2][2][Bb*Dd];       // [dir][parity][b*256+d]
__device__ float g_hseq[2][Tt*Bb*Dd];       // dir1 stored time-reversed
__device__ float g_outext[4224*512];        // rows b*T+t = outputs ; rows 4096+b = [hT_f|hT_b]
__device__ float g_roext[4224*256];         // rows b*T+t = rnn_out ; rows 4096+b = hidden
__device__ float g_E[4][Bb*Ll*Dd];          // embed_bag + add_lm per table
__device__ float g_u[Bb*Dd];
__device__ float g_logit[Bb*Ll];
__device__ float g_prob[Bb*Ll];
__device__ float g_okp[4][Bb*Dd];
__device__ unsigned g_flag[2][64];

// ---------------- init ----------------
__global__ void k_init() {
    int tid = threadIdx.x;
    for (int i = tid; i < Bb*Dd; i += 256) { g_hbuf[0][0][i] = 0.f; g_hbuf[1][0][i] = 0.f; }
    if (tid < 64) { g_flag[0][tid] = 0u; g_flag[1][tid] = 0u; }
}

// ---------------- conv embed-bag -> x[T,B,D] ----------------
__global__ void k_embed_conv(const int* __restrict__ conv, const float* __restrict__ tab) {
    int bid = blockIdx.x;                  // b*T + t
    int b = bid >> 7, t = bid & 127;
    int d = threadIdx.x;
    const int* ip = conv + (size_t)bid * 4;
    float s = tab[(size_t)ip[0]*Dd + d] + tab[(size_t)ip[1]*Dd + d]
            + tab[(size_t)ip[2]*Dd + d] + tab[(size_t)ip[3]*Dd + d];
    g_x[((size_t)t*Bb + b)*Dd + d] = s;
}

// ---------------- GEMM: C[M,N] = A[M,K] * Bw[N,K]^T + bias (FFMA2) ----------------
// mode 0/1: A=g_x (4096x256) -> g_gx[mode] (N=768)
// mode 2  : A=g_outext (4224x512) -> g_roext (N=256)
__global__ __launch_bounds__(256) void k_gemm(const float* __restrict__ Bw,
                                              const float* __restrict__ bias, int mode) {
    __shared__ float2 as2[16][128];     // A tile with每 element duplicated (a,a)
    __shared__ float  bs[16][64];
    const float* A; float* C; int Kd, Nd;
    if (mode < 2) { A = g_x;      C = g_gx[mode]; Kd = 256; Nd = 768; }
    else          { A = g_outext; C = g_roext;    Kd = 512; Nd = 256; }

    int tid = threadIdx.x;
    int j = tid & 15;          // n-group (4 cols -> 2 packed col-pairs)
    int i = tid >> 4;          // m-group (8 rows)
    int bm = blockIdx.x * 128;
    int bn = blockIdx.y * 64;

    unsigned long long acc[8][2];
    #pragma unroll
    for (int r = 0; r < 8; r++) { acc[r][0] = 0ull; acc[r][1] = 0ull; }

    for (int k0 = 0; k0 < Kd; k0 += 16) {
        // A tile (128x16) duplicated: 512 float4 source slots
        #pragma unroll
        for (int p = 0; p < 2; p++) {
            int s = tid + p*256;
            int m = s >> 2, kc = s & 3;
            float4 v = *(const float4*)&A[(size_t)(bm + m)*Kd + k0 + kc*4];
            as2[kc*4+0][m] = make_float2(v.x, v.x);
            as2[kc*4+1][m] = make_float2(v.y, v.y);
            as2[kc*4+2][m] = make_float2(v.z, v.z);
            as2[kc*4+3][m] = make_float2(v.w, v.w);
        }
        // B tile (64x16)
        {
            int s = tid;
            int n = s >> 2, kc = s & 3;
            float4 v = *(const float4*)&Bw[(size_t)(bn + n)*Kd + k0 + kc*4];
            bs[kc*4+0][n] = v.x; bs[kc*4+1][n] = v.y; bs[kc*4+2][n] = v.z; bs[kc*4+3][n] = v.w;
        }
        __syncthreads();
        #pragma unroll
        for (int kk = 0; kk < 16; kk++) {
            ulonglong2 a01 = *(const ulonglong2*)&as2[kk][i*8 + 0];
            ulonglong2 a23 = *(const ulonglong2*)&as2[kk][i*8 + 2];
            ulonglong2 a45 = *(const ulonglong2*)&as2[kk][i*8 + 4];
            ulonglong2 a67 = *(const ulonglong2*)&as2[kk][i*8 + 6];
            ulonglong2 bq  = *(const ulonglong2*)&bs[kk][j*4];   // (c0,c1),(c2,c3)
            FFMA2(acc[0][0], a01.x, bq.x); FFMA2(acc[0][1], a01.x, bq.y);
            FFMA2(acc[1][0], a01.y, bq.x); FFMA2(acc[1][1], a01.y, bq.y);
            FFMA2(acc[2][0], a23.x, bq.x); FFMA2(acc[2][1], a23.x, bq.y);
            FFMA2(acc[3][0], a23.y, bq.x); FFMA2(acc[3][1], a23.y, bq.y);
            FFMA2(acc[4][0], a45.x, bq.x); FFMA2(acc[4][1], a45.x, bq.y);
            FFMA2(acc[5][0], a45.y, bq.x); FFMA2(acc[5][1], a45.y, bq.y);
            FFMA2(acc[6][0], a67.x, bq.x); FFMA2(acc[6][1], a67.x, bq.y);
            FFMA2(acc[7][0], a67.y, bq.x); FFMA2(acc[7][1], a67.y, bq.y);
        }
        __syncthreads();
    }
    float4 bb = *(const float4*)&bias[bn + j*4];
    #pragma unroll
    for (int r = 0; r < 8; r++) {
        float2 p0 = *(float2*)&acc[r][0];
        float2 p1 = *(float2*)&acc[r][1];
        float4 o;
        o.x = p0.x + bb.x; o.y = p0.y + bb.y;
        o.z = p1.x + bb.z; o.w = p1.y + bb.w;
        *(float4*)&C[(size_t)(bm + i*8 + r)*Nd + bn + j*4] = o;
    }
}

// ---------------- persistent GRU recurrence ----------------
// grid = 128 (64 CTAs per direction), block = 128 threads
// CTA owns 4 d-columns; thread (warp j = d-col, lane = b).
// Barrier: per-CTA release flag + 64-thread parallel acquire-poll.
__global__ __launch_bounds__(128) void k_recur(const float* __restrict__ Whh_f,
                                               const float* __restrict__ bhh_f,
                                               const float* __restrict__ Whh_b,
                                               const float* __restrict__ bhh_b) {
    int dir = blockIdx.x >> 6;
    int cid = blockIdx.x & 63;
    int d0 = cid * 4;
    const float* Whh = dir ? Whh_b : Whh_f;
    const float* bhh = dir ? bhh_b : bhh_f;

    __shared__ float sW[12][260];
    __shared__ float sh[32][260];

    int tid = threadIdx.x;
    int lane = tid & 31;       // b
    int j = tid >> 5;          // 0..3
    int d = d0 + j;

    for (int r = 0; r < 12; r++) {
        int g = r >> 2, jj = r & 3;
        for (int k = tid; k < 256; k += 128)
            sW[r][k] = Whh[(size_t)(g*256 + d0 + jj)*256 + k];
    }
    float br = bhh[d], bz = bhh[256+d], bnb = bhh[512+d];
    __syncthreads();

    for (int t = 0; t < 128; t++) {
        const float4* hg = (const float4*)g_hbuf[dir][t & 1];
        for (int s = tid; s < 2048; s += 128) {
            float4 v = __ldcg(&hg[s]);
            int b = s >> 6, c = s & 63;
            *((float4*)&sh[b][0] + c) = v;
        }
        __syncthreads();

        int tx = dir ? (127 - t) : t;
        const float* gx = &g_gx[dir][((size_t)tx*Bb + lane)*768];
        float xr = gx[d], xz = gx[256+d], xn = gx[512+d];

        unsigned long long ar2 = 0ull, az2 = 0ull, an2 = 0ull;
        const ulonglong2* h2  = (const ulonglong2*)&sh[lane][0];
        const ulonglong2* wr2 = (const ulonglong2*)&sW[0 + j][0];
        const ulonglong2* wz2 = (const ulonglong2*)&sW[4 + j][0];
        const ulonglong2* wn2 = (const ulonglong2*)&sW[8 + j][0];
        #pragma unroll 16
        for (int c = 0; c < 64; c++) {
            ulonglong2 hv = h2[c];
            ulonglong2 wv = wr2[c];
            FFMA2(ar2, hv.x, wv.x); FFMA2(ar2, hv.y, wv.y);
            wv = wz2[c];
            FFMA2(az2, hv.x, wv.x); FFMA2(az2, hv.y, wv.y);
            wv = wn2[c];
            FFMA2(an2, hv.x, wv.x); FFMA2(an2, hv.y, wv.y);
        }
        float2 f;
        f = *(float2*)&ar2; float ar = f.x + f.y;
        f = *(float2*)&az2; float az = f.x + f.y;
        f = *(float2*)&an2; float an = f.x + f.y;

        float rr = 1.f/(1.f + expf(-(xr + ar + br)));
        float zz = 1.f/(1.f + expf(-(xz + az + bz)));
        float nn = tanhf(xn + rr*(an + bnb));
        float hprev = sh[lane][d];
        float hnew = (1.f - zz)*nn + zz*hprev;

        g_hbuf[dir][(t + 1) & 1][lane*Dd + d] = hnew;
        g_hseq[dir][((size_t)tx*Bb + lane)*Dd + d] = hnew;

        __threadfence();
        __syncthreads();
        if (tid == 0) {
            asm volatile("st.release.gpu.global.u32 [%0], %1;"
                         :: "l"(&g_flag[dir][cid]), "r"((unsigned)(t+1)) : "memory");
        }
        if (tid < 64) {
            unsigned v;
            do {
                asm volatile("ld.acquire.gpu.global.u32 %0, [%1];"
                             : "=r"(v) : "l"(&g_flag[dir][tid]) : "memory");
            } while (v < (unsigned)(t + 1));
        }
        __syncthreads();
    }
}

// ---------------- pack outputs / hT into extended matrix ----------------
__global__ void k_pack() {
    int bid = blockIdx.x;      // 0..4127
    int d = threadIdx.x;
    float* o = g_outext + (size_t)bid*512;
    if (bid < 4096) {
        int b = bid >> 7, t = bid & 127;
        o[d]       = g_hseq[0][((size_t)t*Bb + b)*Dd + d];
        o[256 + d] = g_hseq[1][((size_t)t*Bb + b)*Dd + d];
    } else {
        int b = bid - 4096;
        o[d]       = g_hbuf[0][0][b*Dd + d];
        o[256 + d] = g_hbuf[1][0][b*Dd + d];
    }
}

// ---------------- memory embed-bag + add_lm, fused over 4 tables ----------------
__global__ void k_embed_mem(const int* __restrict__ src, const float* __restrict__ Ct,
                            const int* __restrict__ kb, const int* __restrict__ cl) {
    int bid = blockIdx.x;                 // b*512 + l
    int b = bid >> 9, l = bid & 511;
    int d = threadIdx.x;
    const int* ip = src + (size_t)bid * 4;
    int i0 = ip[0], i1 = ip[1], i2 = ip[2], i3 = ip[3];
    int rel = l - kb[b];
    float add = (rel >= 0 && rel < cl[b]) ? g_roext[((size_t)b*Tt + rel)*Dd + d] : 0.f;
    #pragma unroll
    for (int k = 0; k < 4; k++) {
        const float* tab = Ct + (size_t)k*VOC*Dd;
        float s = tab[(size_t)i0*Dd + d] + tab[(size_t)i1*Dd + d]
                + tab[(size_t)i2*Dd + d] + tab[(size_t)i3*Dd + d];
        g_E[k][(size_t)bid*Dd + d] = s + add;
    }
}

__global__ void k_init_u() {
    int b = blockIdx.x, d = threadIdx.x;
    g_u[b*Dd + d] = g_roext[(size_t)(4096 + b)*Dd + d];
}

// ---------------- hop kernels ----------------
__global__ void k_logit(int h) {
    int wid = blockIdx.x*8 + (threadIdx.x >> 5);
    int lane = threadIdx.x & 31;
    int b = wid >> 9, l = wid & 511;
    const float4* E4 = (const float4*)(g_E[h] + ((size_t)(b*Ll + l))*Dd);
    const float4* u4 = (const float4*)(g_u + b*Dd);
    float4 e0 = E4[lane],      a0 = u4[lane];
    float4 e1 = E4[lane + 32], a1 = u4[lane + 32];
    float s = e0.x*a0.x + e0.y*a0.y + e0.z*a0.z + e0.w*a0.w
            + e1.x*a1.x + e1.y*a1.y + e1.z*a1.z + e1.w*a1.w;
    #pragma unroll
    for (int o = 16; o; o >>= 1) s += __shfl_down_sync(0xffffffffu, s, o);
    if (lane == 0) g_logit[b*Ll + l] = s;
}

__global__ void k_softmax() {
    __shared__ float red[256];
    int b = blockIdx.x, tid = threadIdx.x;
    float v0 = g_logit[b*Ll + tid];
    float v1 = g_logit[b*Ll + 256 + tid];
    red[tid] = fmaxf(v0, v1);
    __syncthreads();
    for (int s = 128; s > 0; s >>= 1) {
        if (tid < s) red[tid] = fmaxf(red[tid], red[tid + s]);
        __syncthreads();
    }
    float m = red[0];
    __syncthreads();
    float e0 = expf(v0 - m), e1 = expf(v1 - m);
    red[tid] = e0 + e1;
    __syncthreads();
    for (int s = 128; s > 0; s >>= 1) {
        if (tid < s) red[tid] += red[tid + s];
        __syncthreads();
    }
    float inv = 1.f / red[0];
    g_prob[b*Ll + tid]       = e0 * inv;
    g_prob[b*Ll + 256 + tid] = e1 * inv;
}

__global__ void k_okpart(int h) {
    __shared__ float sp[128];
    int b = blockIdx.x >> 2, ch = blockIdx.x & 3;
    int d = threadIdx.x;
    if (d < 128) sp[d] = g_prob[b*Ll + ch*128 + d];
    __syncthreads();
    const float* Eb = g_E[h + 1] + (size_t)b*Ll*Dd + (size_t)ch*128*Dd + d;
    float acc = 0.f;
    #pragma unroll 8
    for (int l = 0; l < 128; l++) acc += Eb[(size_t)l*Dd] * sp[l];
    g_okp[ch][b*Dd + d] = acc;
}

__global__ void k_okred() {
    int b = blockIdx.x, d = threadIdx.x;
    g_u[b*Dd + d] += ((g_okp[0][b*Dd + d] + g_okp[1][b*Dd + d])
                    + g_okp[2][b*Dd + d]) + g_okp[3][b*Dd + d];
}

// ---------------- outputs ----------------
__global__ void k_sigmoid(float* __restrict__ out) {
    int i = blockIdx.x*256 + threadIdx.x;   // 0..16383
    out[i] = 1.f/(1.f + expf(-g_logit[i]));
}

__global__ void k_proj(const float* __restrict__ pw, const float* __restrict__ pb,
                       float* __restrict__ out) {
    int wid = blockIdx.x*8 + (threadIdx.x >> 5);   // 0..8191
    int lane = threadIdx.x & 31;
    int b = wid >> 8, d = wid & 255;
    const float4* w4 = (const float4*)(pw + (size_t)d*512);
    const float4* h4 = (const float4*)(g_roext + (size_t)(4096 + b)*Dd);
    const float4* u4 = (const float4*)(g_u + b*Dd);
    float4 wv, av; float s = 0.f;
    wv = w4[lane];      av = h4[lane];      s += wv.x*av.x + wv.y*av.y + wv.z*av.z + wv.w*av.w;
    wv = w4[lane+32];   av = h4[lane+32];   s += wv.x*av.x + wv.y*av.y + wv.z*av.z + wv.w*av.w;
    wv = w4[lane+64];   av = u4[lane];      s += wv.x*av.x + wv.y*av.y + wv.z*av.z + wv.w*av.w;
    wv = w4[lane+96];   av = u4[lane+32];   s += wv.x*av.x + wv.y*av.y + wv.z*av.z + wv.w*av.w;
    #pragma unroll
    for (int o = 16; o; o >>= 1) s += __shfl_down_sync(0xffffffffu, s, o);
    if (lane == 0) out[16384 + b*Dd + d] = fmaxf(0.f, s + pb[d]);
}

// ---------------- launch ----------------
extern "C" void kernel_launch(void* const* d_in, const int* in_sizes, int n_in,
                              void* d_out, int out_size) {
    (void)in_sizes; (void)n_in; (void)out_size;
    const int*   conv    = (const int*)d_in[0];
    const int*   src     = (const int*)d_in[1];
    const int*   kb      = (const int*)d_in[2];
    const int*   cl      = (const int*)d_in[3];
    const float* emb_ctx = (const float*)d_in[4];
    const float* Ct      = (const float*)d_in[5];
    const float* Wih_f   = (const float*)d_in[6];
    const float* Whh_f   = (const float*)d_in[7];
    const float* bih_f   = (const float*)d_in[8];
    const float* bhh_f   = (const float*)d_in[9];
    const float* Wih_b   = (const float*)d_in[10];
    const float* Whh_b   = (const float*)d_in[11];
    const float* bih_b   = (const float*)d_in[12];
    const float* bhh_b   = (const float*)d_in[13];
    const float* W_w     = (const float*)d_in[14];
    const float* W_b     = (const float*)d_in[15];
    const float* proj_w  = (const float*)d_in[16];
    const float* proj_b  = (const float*)d_in[17];
    float* out = (float*)d_out;

    k_init<<<1, 256>>>();
    k_embed_conv<<<4096, 256>>>(conv, emb_ctx);
    k_gemm<<<dim3(32, 12), 256>>>(Wih_f, bih_f, 0);
    k_gemm<<<dim3(32, 12), 256>>>(Wih_b, bih_b, 1);
    k_recur<<<128, 128>>>(Whh_f, bhh_f, Whh_b, bhh_b);
    k_pack<<<4128, 256>>>();
    k_gemm<<<dim3(33, 4), 256>>>(W_w, W_b, 2);
    k_embed_mem<<<16384, 256>>>(src, Ct, kb, cl);
    k_init_u<<<32, 256>>>();
    for (int h = 0; h < 3; h++) {
        k_logit<<<2048, 256>>>(h);
        k_softmax<<<32, 256>>>();
        k_okpart<<<128, 256>>>(h);
        k_okred<<<32, 256>>>();
    }
    k_sigmoid<<<64, 256>>>(out);
    k_proj<<<1024, 256>>>(proj_w, proj_b, out);
}

// round 15
// speedup vs baseline: 1.8576x; 1.8576x over previous
#include <cuda_runtime.h>
#include <math.h>

#define Bb 32
#define Tt 128
#define Ll 512
#define Dd 256
#define VOC 32000

// ---------------- scratch ----------------
__device__ float g_x[Tt*Bb*Dd];             // [t*B+b][d]
__device__ float g_gx[2][Tt*Bb*768];        // [dir][t*B+b][gate*256+d]
__device__ float g_hbuf[2][2][Bb*Dd];       // [dir][parity][b*256+d]
__device__ float g_outext[4224*512];        // rows b*T+t = outputs ; rows 4096+b = [hT_f|hT_b]
__device__ float g_roext[4224*256];         // rows b*T+t = rnn_out ; rows 4096+b = hidden
__device__ float g_E[4][Bb*Ll*Dd];          // embed_bag + add_lm per table
__device__ float g_u[Bb*Dd];
__device__ float g_logit[Bb*Ll];
__device__ float g_prob[Bb*Ll];
__device__ float g_okp[4][Bb*Dd];
__device__ unsigned g_bar[2];

// ---------------- init ----------------
__global__ void k_init() {
    int tid = threadIdx.x;
    for (int i = tid; i < Bb*Dd; i += 256) { g_hbuf[0][0][i] = 0.f; g_hbuf[1][0][i] = 0.f; }
    if (tid < 2) g_bar[tid] = 0u;
}

// ---------------- conv embed-bag -> x[T,B,D] ----------------
__global__ void k_embed_conv(const int* __restrict__ conv, const float* __restrict__ tab) {
    int bid = blockIdx.x;                  // b*T + t
    int b = bid >> 7, t = bid & 127;
    int d = threadIdx.x;
    const int* ip = conv + (size_t)bid * 4;
    float s = tab[(size_t)ip[0]*Dd + d] + tab[(size_t)ip[1]*Dd + d]
            + tab[(size_t)ip[2]*Dd + d] + tab[(size_t)ip[3]*Dd + d];
    g_x[((size_t)t*Bb + b)*Dd + d] = s;
}

// ---------------- GEMM: C[M,N] = A[M,K] * Bw[N,K]^T + bias ----------------
// mode 0/1: A=g_x (4096x256) -> g_gx[mode] (N=768)
// mode 2  : A=g_outext (4224x512) -> g_roext (N=256)
__global__ __launch_bounds__(256) void k_gemm(const float* __restrict__ Bw,
                                              const float* __restrict__ bias, int mode) {
    __shared__ float as[16][128];
    __shared__ float bs[16][64];
    const float* A; float* C; int Kd, Nd;
    if (mode < 2) { A = g_x;      C = g_gx[mode]; Kd = 256; Nd = 768; }
    else          { A = g_outext; C = g_roext;    Kd = 512; Nd = 256; }

    int tid = threadIdx.x;
    int j = tid & 15;          // n-group
    int i = tid >> 4;          // m-group
    int bm = blockIdx.x * 128;
    int bn = blockIdx.y * 64;

    float acc[8][4];
    #pragma unroll
    for (int r = 0; r < 8; r++)
        #pragma unroll
        for (int c = 0; c < 4; c++) acc[r][c] = 0.f;

    for (int k0 = 0; k0 < Kd; k0 += 16) {
        #pragma unroll
        for (int p = 0; p < 2; p++) {
            int s = tid + p*256;
            int m = s >> 2, kc = s & 3;
            float4 v = *(const float4*)&A[(size_t)(bm + m)*Kd + k0 + kc*4];
            as[kc*4+0][m] = v.x; as[kc*4+1][m] = v.y; as[kc*4+2][m] = v.z; as[kc*4+3][m] = v.w;
        }
        {
            int s = tid;
            int n = s >> 2, kc = s & 3;
            float4 v = *(const float4*)&Bw[(size_t)(bn + n)*Kd + k0 + kc*4];
            bs[kc*4+0][n] = v.x; bs[kc*4+1][n] = v.y; bs[kc*4+2][n] = v.z; bs[kc*4+3][n] = v.w;
        }
        __syncthreads();
        #pragma unroll
        for (int kk = 0; kk < 16; kk++) {
            float4 a0 = *(const float4*)&as[kk][i*8];
            float4 a1 = *(const float4*)&as[kk][i*8+4];
            float4 bv = *(const float4*)&bs[kk][j*4];
            float am[8] = {a0.x,a0.y,a0.z,a0.w,a1.x,a1.y,a1.z,a1.w};
            float bn4[4] = {bv.x,bv.y,bv.z,bv.w};
            #pragma unroll
            for (int r = 0; r < 8; r++)
                #pragma unroll
                for (int c = 0; c < 4; c++) acc[r][c] += am[r]*bn4[c];
        }
        __syncthreads();
    }
    float4 bb = *(const float4*)&bias[bn + j*4];
    #pragma unroll
    for (int r = 0; r < 8; r++) {
        float4 o;
        o.x = acc[r][0] + bb.x; o.y = acc[r][1] + bb.y;
        o.z = acc[r][2] + bb.z; o.w = acc[r][3] + bb.w;
        *(float4*)&C[(size_t)(bm + i*8 + r)*Nd + bn + j*4] = o;
    }
}

// ---------------- persistent GRU recurrence (writes g_outext directly) ----------------
// grid = 128 (64 CTAs per direction), block = 128 threads
// CTA owns 4 d-columns; thread (warp j = d-col, lane = b) computes r/z/n dots.
__global__ __launch_bounds__(128) void k_recur(const float* __restrict__ Whh_f,
                                               const float* __restrict__ bhh_f,
                                               const float* __restrict__ Whh_b,
                                               const float* __restrict__ bhh_b) {
    int dir = blockIdx.x >> 6;
    int cid = blockIdx.x & 63;
    int d0 = cid * 4;
    const float* Whh = dir ? Whh_b : Whh_f;
    const float* bhh = dir ? bhh_b : bhh_f;

    __shared__ float sW[12][260];
    __shared__ float sh[32][260];

    int tid = threadIdx.x;
    int lane = tid & 31;       // b
    int j = tid >> 5;          // 0..3
    int d = d0 + j;

    for (int r = 0; r < 12; r++) {
        int g = r >> 2, jj = r & 3;
        for (int k = tid; k < 256; k += 128)
            sW[r][k] = Whh[(size_t)(g*256 + d0 + jj)*256 + k];
    }
    float br = bhh[d], bz = bhh[256+d], bnb = bhh[512+d];
    __syncthreads();

    for (int t = 0; t < 128; t++) {
        const float4* hg = (const float4*)g_hbuf[dir][t & 1];
        for (int s = tid; s < 2048; s += 128) {
            float4 v = __ldcg(&hg[s]);
            int b = s >> 6, c = s & 63;
            *((float4*)&sh[b][0] + c) = v;
        }
        __syncthreads();

        float ar = 0.f, az = 0.f, an = 0.f;
        const float4* h4 = (const float4*)&sh[lane][0];
        const float4* wr = (const float4*)&sW[0 + j][0];
        const float4* wz = (const float4*)&sW[4 + j][0];
        const float4* wn = (const float4*)&sW[8 + j][0];
        #pragma unroll 16
        for (int c = 0; c < 64; c++) {
            float4 hv = h4[c];
            float4 w1 = wr[c];
            ar += hv.x*w1.x + hv.y*w1.y + hv.z*w1.z + hv.w*w1.w;
            float4 w2 = wz[c];
            az += hv.x*w2.x + hv.y*w2.y + hv.z*w2.z + hv.w*w2.w;
            float4 w3 = wn[c];
            an += hv.x*w3.x + hv.y*w3.y + hv.z*w3.z + hv.w*w3.w;
        }

        int tx = dir ? (127 - t) : t;   // output time index (backward stores reversed)
        const float* gx = &g_gx[dir][((size_t)tx*Bb + lane)*768];
        float xr = gx[d], xz = gx[256+d], xn = gx[512+d];
        float rr = 1.f/(1.f + expf(-(xr + ar + br)));
        float zz = 1.f/(1.f + expf(-(xz + az + bz)));
        float nn = tanhf(xn + rr*(an + bnb));
        float hprev = sh[lane][d];
        float hnew = (1.f - zz)*nn + zz*hprev;

        g_hbuf[dir][(t + 1) & 1][lane*Dd + d] = hnew;
        // outputs row = b*T + tx, col = dir*256 + d   (fused pack)
        g_outext[((size_t)lane*Tt + tx)*512 + dir*256 + d] = hnew;
        if (t == 127)   // hT rows
            g_outext[(size_t)(4096 + lane)*512 + dir*256 + d] = hnew;

        __threadfence();
        __syncthreads();
        if (tid == 0) {
            atomicAdd(&g_bar[dir], 1u);
            unsigned target = (unsigned)(t + 1) * 64u;
            while (*((volatile unsigned*)&g_bar[dir]) < target) { }
        }
        __syncthreads();
    }
}

// ---------------- memory embed-bag + add_lm, fused over 4 tables ----------------
__global__ void k_embed_mem(const int* __restrict__ src, const float* __restrict__ Ct,
                            const int* __restrict__ kb, const int* __restrict__ cl) {
    int bid = blockIdx.x;                 // b*512 + l
    int b = bid >> 9, l = bid & 511;
    int d = threadIdx.x;
    const int* ip = src + (size_t)bid * 4;
    int i0 = ip[0], i1 = ip[1], i2 = ip[2], i3 = ip[3];
    int rel = l - kb[b];
    float add = (rel >= 0 && rel < cl[b]) ? g_roext[((size_t)b*Tt + rel)*Dd + d] : 0.f;
    #pragma unroll
    for (int k = 0; k < 4; k++) {
        const float* tab = Ct + (size_t)k*VOC*Dd;
        float s = tab[(size_t)i0*Dd + d] + tab[(size_t)i1*Dd + d]
                + tab[(size_t)i2*Dd + d] + tab[(size_t)i3*Dd + d];
        g_E[k][(size_t)bid*Dd + d] = s + add;
    }
}

__global__ void k_init_u() {
    int b = blockIdx.x, d = threadIdx.x;
    g_u[b*Dd + d] = g_roext[(size_t)(4096 + b)*Dd + d];
}

// ---------------- hop kernels ----------------
__global__ void k_logit(int h) {
    int wid = blockIdx.x*8 + (threadIdx.x >> 5);
    int lane = threadIdx.x & 31;
    int b = wid >> 9, l = wid & 511;
    const float4* E4 = (const float4*)(g_E[h] + ((size_t)(b*Ll + l))*Dd);
    const float4* u4 = (const float4*)(g_u + b*Dd);
    float4 e0 = E4[lane],      a0 = u4[lane];
    float4 e1 = E4[lane + 32], a1 = u4[lane + 32];
    float s = e0.x*a0.x + e0.y*a0.y + e0.z*a0.z + e0.w*a0.w
            + e1.x*a1.x + e1.y*a1.y + e1.z*a1.z + e1.w*a1.w;
    #pragma unroll
    for (int o = 16; o; o >>= 1) s += __shfl_down_sync(0xffffffffu, s, o);
    if (lane == 0) g_logit[b*Ll + l] = s;
}

__global__ void k_softmax() {
    __shared__ float red[256];
    int b = blockIdx.x, tid = threadIdx.x;
    float v0 = g_logit[b*Ll + tid];
    float v1 = g_logit[b*Ll + 256 + tid];
    red[tid] = fmaxf(v0, v1);
    __syncthreads();
    for (int s = 128; s > 0; s >>= 1) {
        if (tid < s) red[tid] = fmaxf(red[tid], red[tid + s]);
        __syncthreads();
    }
    float m = red[0];
    __syncthreads();
    float e0 = expf(v0 - m), e1 = expf(v1 - m);
    red[tid] = e0 + e1;
    __syncthreads();
    for (int s = 128; s > 0; s >>= 1) {
        if (tid < s) red[tid] += red[tid + s];
        __syncthreads();
    }
    float inv = 1.f / red[0];
    g_prob[b*Ll + tid]       = e0 * inv;
    g_prob[b*Ll + 256 + tid] = e1 * inv;
}

__global__ void k_okpart(int h) {
    __shared__ float sp[128];
    int b = blockIdx.x >> 2, ch = blockIdx.x & 3;
    int d = threadIdx.x;
    if (d < 128) sp[d] = g_prob[b*Ll + ch*128 + d];
    __syncthreads();
    const float* Eb = g_E[h + 1] + (size_t)b*Ll*Dd + (size_t)ch*128*Dd + d;
    float acc = 0.f;
    #pragma unroll 8
    for (int l = 0; l < 128; l++) acc += Eb[(size_t)l*Dd] * sp[l];
    g_okp[ch][b*Dd + d] = acc;
}

__global__ void k_okred() {
    int b = blockIdx.x, d = threadIdx.x;
    g_u[b*Dd + d] += ((g_okp[0][b*Dd + d] + g_okp[1][b*Dd + d])
                    + g_okp[2][b*Dd + d]) + g_okp[3][b*Dd + d];
}

// ---------------- outputs ----------------
__global__ void k_sigmoid(float* __restrict__ out) {
    int i = blockIdx.x*256 + threadIdx.x;   // 0..16383
    out[i] = 1.f/(1.f + expf(-g_logit[i]));
}

__global__ void k_proj(const float* __restrict__ pw, const float* __restrict__ pb,
                       float* __restrict__ out) {
    int wid = blockIdx.x*8 + (threadIdx.x >> 5);   // 0..8191
    int lane = threadIdx.x & 31;
    int b = wid >> 8, d = wid & 255;
    const float4* w4 = (const float4*)(pw + (size_t)d*512);
    const float4* h4 = (const float4*)(g_roext + (size_t)(4096 + b)*Dd);
    const float4* u4 = (const float4*)(g_u + b*Dd);
    float4 wv, av; float s = 0.f;
    wv = w4[lane];      av = h4[lane];      s += wv.x*av.x + wv.y*av.y + wv.z*av.z + wv.w*av.w;
    wv = w4[lane+32];   av = h4[lane+32];   s += wv.x*av.x + wv.y*av.y + wv.z*av.z + wv.w*av.w;
    wv = w4[lane+64];   av = u4[lane];      s += wv.x*av.x + wv.y*av.y + wv.z*av.z + wv.w*av.w;
    wv = w4[lane+96];   av = u4[lane+32];   s += wv.x*av.x + wv.y*av.y + wv.z*av.z + wv.w*av.w;
    #pragma unroll
    for (int o = 16; o; o >>= 1) s += __shfl_down_sync(0xffffffffu, s, o);
    if (lane == 0) out[16384 + b*Dd + d] = fmaxf(0.f, s + pb[d]);
}

// ---------------- launch ----------------
extern "C" void kernel_launch(void* const* d_in, const int* in_sizes, int n_in,
                              void* d_out, int out_size) {
    (void)in_sizes; (void)n_in; (void)out_size;
    const int*   conv    = (const int*)d_in[0];
    const int*   src     = (const int*)d_in[1];
    const int*   kb      = (const int*)d_in[2];
    const int*   cl      = (const int*)d_in[3];
    const float* emb_ctx = (const float*)d_in[4];
    const float* Ct      = (const float*)d_in[5];
    const float* Wih_f   = (const float*)d_in[6];
    const float* Whh_f   = (const float*)d_in[7];
    const float* bih_f   = (const float*)d_in[8];
    const float* bhh_f   = (const float*)d_in[9];
    const float* Wih_b   = (const float*)d_in[10];
    const float* Whh_b   = (const float*)d_in[11];
    const float* bih_b   = (const float*)d_in[12];
    const float* bhh_b   = (const float*)d_in[13];
    const float* W_w     = (const float*)d_in[14];
    const float* W_b     = (const float*)d_in[15];
    const float* proj_w  = (const float*)d_in[16];
    const float* proj_b  = (const float*)d_in[17];
    float* out = (float*)d_out;

    k_init<<<1, 256>>>();
    k_embed_conv<<<4096, 256>>>(conv, emb_ctx);
    k_gemm<<<dim3(32, 12), 256>>>(Wih_f, bih_f, 0);
    k_gemm<<<dim3(32, 12), 256>>>(Wih_b, bih_b, 1);
    k_recur<<<128, 128>>>(Whh_f, bhh_f, Whh_b, bhh_b);
    k_gemm<<<dim3(33, 4), 256>>>(W_w, W_b, 2);
    k_embed_mem<<<16384, 256>>>(src, Ct, kb, cl);
    k_init_u<<<32, 256>>>();
    for (int h = 0; h < 3; h++) {
        k_logit<<<2048, 256>>>(h);
        k_softmax<<<32, 256>>>();
        k_okpart<<<128, 256>>>(h);
        k_okred<<<32, 256>>>();
    }
    k_sigmoid<<<64, 256>>>(out);
    k_proj<<<1024, 256>>>(proj_w, proj_b, out);
}

// round 16
// speedup vs baseline: 1.9301x; 1.0390x over previous
#include <cuda_runtime.h>
#include <math.h>

#define Bb 32
#define Tt 128
#define Ll 512
#define Dd 256
#define VOC 32000

#define FFMA2(acc, a, b) asm("fma.rn.f32x2 %0, %1, %2, %0;" : "+l"(acc) : "l"(a), "l"(b))

// ---------------- scratch ----------------
__device__ float g_x[Tt*Bb*Dd];             // [t*B+b][d]
__device__ float g_gx[2][Tt*Bb*768];        // [dir][t*B+b][gate*256+d]
__device__ float g_hbuf[2][2][Bb*Dd];       // [dir][parity][b*256+d]
__device__ float g_outext[4224*512];        // rows b*T+t = outputs ; rows 4096+b = [hT_f|hT_b]
__device__ float g_roext[4224*256];         // rows b*T+t = rnn_out ; rows 4096+b = hidden
__device__ float g_E[4][Bb*Ll*Dd];          // embed_bag + add_lm per table
__device__ float g_u[Bb*Dd];
__device__ float g_logit[Bb*Ll];
__device__ float g_prob[Bb*Ll];
__device__ float g_okp[4][Bb*Dd];
__device__ unsigned g_bar[2];

// ---------------- init ----------------
__global__ void k_init() {
    int tid = threadIdx.x;
    for (int i = tid; i < Bb*Dd; i += 256) { g_hbuf[0][0][i] = 0.f; g_hbuf[1][0][i] = 0.f; }
    if (tid < 2) g_bar[tid] = 0u;
}

// ---------------- conv embed-bag -> x[T,B,D] ----------------
__global__ void k_embed_conv(const int* __restrict__ conv, const float* __restrict__ tab) {
    int bid = blockIdx.x;                  // b*T + t
    int b = bid >> 7, t = bid & 127;
    int d = threadIdx.x;
    const int* ip = conv + (size_t)bid * 4;
    float s = tab[(size_t)ip[0]*Dd + d] + tab[(size_t)ip[1]*Dd + d]
            + tab[(size_t)ip[2]*Dd + d] + tab[(size_t)ip[3]*Dd + d];
    g_x[((size_t)t*Bb + b)*Dd + d] = s;
}

// ---------------- GEMM: C[M,N] = A[M,K] * Bw[N,K]^T + bias ----------------
__global__ __launch_bounds__(256) void k_gemm(const float* __restrict__ Bw,
                                              const float* __restrict__ bias, int mode) {
    __shared__ float as[16][128];
    __shared__ float bs[16][64];
    const float* A; float* C; int Kd, Nd;
    if (mode < 2) { A = g_x;      C = g_gx[mode]; Kd = 256; Nd = 768; }
    else          { A = g_outext; C = g_roext;    Kd = 512; Nd = 256; }

    int tid = threadIdx.x;
    int j = tid & 15;
    int i = tid >> 4;
    int bm = blockIdx.x * 128;
    int bn = blockIdx.y * 64;

    float acc[8][4];
    #pragma unroll
    for (int r = 0; r < 8; r++)
        #pragma unroll
        for (int c = 0; c < 4; c++) acc[r][c] = 0.f;

    for (int k0 = 0; k0 < Kd; k0 += 16) {
        #pragma unroll
        for (int p = 0; p < 2; p++) {
            int s = tid + p*256;
            int m = s >> 2, kc = s & 3;
            float4 v = *(const float4*)&A[(size_t)(bm + m)*Kd + k0 + kc*4];
            as[kc*4+0][m] = v.x; as[kc*4+1][m] = v.y; as[kc*4+2][m] = v.z; as[kc*4+3][m] = v.w;
        }
        {
            int s = tid;
            int n = s >> 2, kc = s & 3;
            float4 v = *(const float4*)&Bw[(size_t)(bn + n)*Kd + k0 + kc*4];
            bs[kc*4+0][n] = v.x; bs[kc*4+1][n] = v.y; bs[kc*4+2][n] = v.z; bs[kc*4+3][n] = v.w;
        }
        __syncthreads();
        #pragma unroll
        for (int kk = 0; kk < 16; kk++) {
            float4 a0 = *(const float4*)&as[kk][i*8];
            float4 a1 = *(const float4*)&as[kk][i*8+4];
            float4 bv = *(const float4*)&bs[kk][j*4];
            float am[8] = {a0.x,a0.y,a0.z,a0.w,a1.x,a1.y,a1.z,a1.w};
            float bn4[4] = {bv.x,bv.y,bv.z,bv.w};
            #pragma unroll
            for (int r = 0; r < 8; r++)
                #pragma unroll
                for (int c = 0; c < 4; c++) acc[r][c] += am[r]*bn4[c];
        }
        __syncthreads();
    }
    float4 bb = *(const float4*)&bias[bn + j*4];
    #pragma unroll
    for (int r = 0; r < 8; r++) {
        float4 o;
        o.x = acc[r][0] + bb.x; o.y = acc[r][1] + bb.y;
        o.z = acc[r][2] + bb.z; o.w = acc[r][3] + bb.w;
        *(float4*)&C[(size_t)(bm + i*8 + r)*Nd + bn + j*4] = o;
    }
}

// ---------------- persistent GRU recurrence (FFMA2 dot, atomic barrier) ----------------
__global__ __launch_bounds__(128) void k_recur(const float* __restrict__ Whh_f,
                                               const float* __restrict__ bhh_f,
                                               const float* __restrict__ Whh_b,
                                               const float* __restrict__ bhh_b) {
    int dir = blockIdx.x >> 6;
    int cid = blockIdx.x & 63;
    int d0 = cid * 4;
    const float* Whh = dir ? Whh_b : Whh_f;
    const float* bhh = dir ? bhh_b : bhh_f;

    __shared__ float sW[12][260];
    __shared__ float sh[32][260];

    int tid = threadIdx.x;
    int lane = tid & 31;       // b
    int j = tid >> 5;          // 0..3
    int d = d0 + j;

    for (int r = 0; r < 12; r++) {
        int g = r >> 2, jj = r & 3;
        for (int k = tid; k < 256; k += 128)
            sW[r][k] = Whh[(size_t)(g*256 + d0 + jj)*256 + k];
    }
    float br = bhh[d], bz = bhh[256+d], bnb = bhh[512+d];
    __syncthreads();

    for (int t = 0; t < 128; t++) {
        int tx = dir ? (127 - t) : t;
        // hoist gx LDGs: latency overlaps smem fill + dot
        const float* gx = &g_gx[dir][((size_t)tx*Bb + lane)*768];
        float xr = __ldg(&gx[d]), xz = __ldg(&gx[256+d]), xn = __ldg(&gx[512+d]);

        const float4* hg = (const float4*)g_hbuf[dir][t & 1];
        for (int s = tid; s < 2048; s += 128) {
            float4 v = __ldcg(&hg[s]);
            int b = s >> 6, c = s & 63;
            *((float4*)&sh[b][0] + c) = v;
        }
        __syncthreads();

        unsigned long long ar2[2] = {0ull,0ull}, az2[2] = {0ull,0ull}, an2[2] = {0ull,0ull};
        const ulonglong2* h2  = (const ulonglong2*)&sh[lane][0];
        const ulonglong2* wr2 = (const ulonglong2*)&sW[0 + j][0];
        const ulonglong2* wz2 = (const ulonglong2*)&sW[4 + j][0];
        const ulonglong2* wn2 = (const ulonglong2*)&sW[8 + j][0];
        #pragma unroll 8
        for (int c = 0; c < 64; c++) {
            ulonglong2 hv = h2[c];
            ulonglong2 wv = wr2[c];
            FFMA2(ar2[0], hv.x, wv.x); FFMA2(ar2[1], hv.y, wv.y);
            wv = wz2[c];
            FFMA2(az2[0], hv.x, wv.x); FFMA2(az2[1], hv.y, wv.y);
            wv = wn2[c];
            FFMA2(an2[0], hv.x, wv.x); FFMA2(an2[1], hv.y, wv.y);
        }
        float2 fa, fb;
        fa = *(float2*)&ar2[0]; fb = *(float2*)&ar2[1];
        float ar = (fa.x + fa.y) + (fb.x + fb.y);
        fa = *(float2*)&az2[0]; fb = *(float2*)&az2[1];
        float az = (fa.x + fa.y) + (fb.x + fb.y);
        fa = *(float2*)&an2[0]; fb = *(float2*)&an2[1];
        float an = (fa.x + fa.y) + (fb.x + fb.y);

        float rr = 1.f/(1.f + expf(-(xr + ar + br)));
        float zz = 1.f/(1.f + expf(-(xz + az + bz)));
        float nn = tanhf(xn + rr*(an + bnb));
        float hprev = sh[lane][d];
        float hnew = (1.f - zz)*nn + zz*hprev;

        g_hbuf[dir][(t + 1) & 1][lane*Dd + d] = hnew;
        g_outext[((size_t)lane*Tt + tx)*512 + dir*256 + d] = hnew;   // fused pack
        if (t == 127)
            g_outext[(size_t)(4096 + lane)*512 + dir*256 + d] = hnew;

        __threadfence();
        __syncthreads();
        if (tid == 0) {
            atomicAdd(&g_bar[dir], 1u);
            unsigned target = (unsigned)(t + 1) * 64u;
            while (*((volatile unsigned*)&g_bar[dir]) < target) { }
        }
        __syncthreads();
    }
}

// ---------------- memory embed-bag + add_lm (fused over 4 tables) + init_u ----------------
__global__ void k_embed_mem(const int* __restrict__ src, const float* __restrict__ Ct,
                            const int* __restrict__ kb, const int* __restrict__ cl) {
    int bid = blockIdx.x;
    int d = threadIdx.x;
    if (bid >= 16384) {                   // fused k_init_u
        int b = bid - 16384;
        g_u[b*Dd + d] = g_roext[(size_t)(4096 + b)*Dd + d];
        return;
    }
    int b = bid >> 9, l = bid & 511;
    const int* ip = src + (size_t)bid * 4;
    int i0 = ip[0], i1 = ip[1], i2 = ip[2], i3 = ip[3];
    int rel = l - kb[b];
    float add = (rel >= 0 && rel < cl[b]) ? g_roext[((size_t)b*Tt + rel)*Dd + d] : 0.f;
    #pragma unroll
    for (int k = 0; k < 4; k++) {
        const float* tab = Ct + (size_t)k*VOC*Dd;
        float s = tab[(size_t)i0*Dd + d] + tab[(size_t)i1*Dd + d]
                + tab[(size_t)i2*Dd + d] + tab[(size_t)i3*Dd + d];
        g_E[k][(size_t)bid*Dd + d] = s + add;
    }
}

// ---------------- hop kernels ----------------
__global__ void k_logit(int h, float* __restrict__ out) {
    int wid = blockIdx.x*8 + (threadIdx.x >> 5);
    int lane = threadIdx.x & 31;
    int b = wid >> 9, l = wid & 511;
    const float4* E4 = (const float4*)(g_E[h] + ((size_t)(b*Ll + l))*Dd);
    const float4* u4 = (const float4*)(g_u + b*Dd);
    float4 e0 = E4[lane],      a0 = u4[lane];
    float4 e1 = E4[lane + 32], a1 = u4[lane + 32];
    float s = e0.x*a0.x + e0.y*a0.y + e0.z*a0.z + e0.w*a0.w
            + e1.x*a1.x + e1.y*a1.y + e1.z*a1.z + e1.w*a1.w;
    #pragma unroll
    for (int o = 16; o; o >>= 1) s += __shfl_down_sync(0xffffffffu, s, o);
    if (lane == 0) {
        g_logit[b*Ll + l] = s;
        if (h == 2)                      // fused global_pointer sigmoid
            out[b*Ll + l] = 1.f/(1.f + expf(-s));
    }
}

__global__ void k_softmax() {
    __shared__ float red[256];
    int b = blockIdx.x, tid = threadIdx.x;
    float v0 = g_logit[b*Ll + tid];
    float v1 = g_logit[b*Ll + 256 + tid];
    red[tid] = fmaxf(v0, v1);
    __syncthreads();
    for (int s = 128; s > 0; s >>= 1) {
        if (tid < s) red[tid] = fmaxf(red[tid], red[tid + s]);
        __syncthreads();
    }
    float m = red[0];
    __syncthreads();
    float e0 = expf(v0 - m), e1 = expf(v1 - m);
    red[tid] = e0 + e1;
    __syncthreads();
    for (int s = 128; s > 0; s >>= 1) {
        if (tid < s) red[tid] += red[tid + s];
        __syncthreads();
    }
    float inv = 1.f / red[0];
    g_prob[b*Ll + tid]       = e0 * inv;
    g_prob[b*Ll + 256 + tid] = e1 * inv;
}

__global__ void k_okpart(int h) {
    __shared__ float sp[128];
    int b = blockIdx.x >> 2, ch = blockIdx.x & 3;
    int d = threadIdx.x;
    if (d < 128) sp[d] = g_prob[b*Ll + ch*128 + d];
    __syncthreads();
    const float* Eb = g_E[h + 1] + (size_t)b*Ll*Dd + (size_t)ch*128*Dd + d;
    float acc = 0.f;
    #pragma unroll 8
    for (int l = 0; l < 128; l++) acc += Eb[(size_t)l*Dd] * sp[l];
    g_okp[ch][b*Dd + d] = acc;
}

__global__ void k_okred() {
    int b = blockIdx.x, d = threadIdx.x;
    g_u[b*Dd + d] += ((g_okp[0][b*Dd + d] + g_okp[1][b*Dd + d])
                    + g_okp[2][b*Dd + d]) + g_okp[3][b*Dd + d];
}

// ---------------- final projection ----------------
__global__ void k_proj(const float* __restrict__ pw, const float* __restrict__ pb,
                       float* __restrict__ out) {
    int wid = blockIdx.x*8 + (threadIdx.x >> 5);   // 0..8191
    int lane = threadIdx.x & 31;
    int b = wid >> 8, d = wid & 255;
    const float4* w4 = (const float4*)(pw + (size_t)d*512);
    const float4* h4 = (const float4*)(g_roext + (size_t)(4096 + b)*Dd);
    const float4* u4 = (const float4*)(g_u + b*Dd);
    float4 wv, av; float s = 0.f;
    wv = w4[lane];      av = h4[lane];      s += wv.x*av.x + wv.y*av.y + wv.z*av.z + wv.w*av.w;
    wv = w4[lane+32];   av = h4[lane+32];   s += wv.x*av.x + wv.y*av.y + wv.z*av.z + wv.w*av.w;
    wv = w4[lane+64];   av = u4[lane];      s += wv.x*av.x + wv.y*av.y + wv.z*av.z + wv.w*av.w;
    wv = w4[lane+96];   av = u4[lane+32];   s += wv.x*av.x + wv.y*av.y + wv.z*av.z + wv.w*av.w;
    #pragma unroll
    for (int o = 16; o; o >>= 1) s += __shfl_down_sync(0xffffffffu, s, o);
    if (lane == 0) out[16384 + b*Dd + d] = fmaxf(0.f, s + pb[d]);
}

// ---------------- launch ----------------
extern "C" void kernel_launch(void* const* d_in, const int* in_sizes, int n_in,
                              void* d_out, int out_size) {
    (void)in_sizes; (void)n_in; (void)out_size;
    const int*   conv    = (const int*)d_in[0];
    const int*   src     = (const int*)d_in[1];
    const int*   kb      = (const int*)d_in[2];
    const int*   cl      = (const int*)d_in[3];
    const float* emb_ctx = (const float*)d_in[4];
    const float* Ct      = (const float*)d_in[5];
    const float* Wih_f   = (const float*)d_in[6];
    const float* Whh_f   = (const float*)d_in[7];
    const float* bih_f   = (const float*)d_in[8];
    const float* bhh_f   = (const float*)d_in[9];
    const float* Wih_b   = (const float*)d_in[10];
    const float* Whh_b   = (const float*)d_in[11];
    const float* bih_b   = (const float*)d_in[12];
    const float* bhh_b   = (const float*)d_in[13];
    const float* W_w     = (const float*)d_in[14];
    const float* W_b     = (const float*)d_in[15];
    const float* proj_w  = (const float*)d_in[16];
    const float* proj_b  = (const float*)d_in[17];
    float* out = (float*)d_out;

    k_init<<<1, 256>>>();
    k_embed_conv<<<4096, 256>>>(conv, emb_ctx);
    k_gemm<<<dim3(32, 12), 256>>>(Wih_f, bih_f, 0);
    k_gemm<<<dim3(32, 12), 256>>>(Wih_b, bih_b, 1);
    k_recur<<<128, 128>>>(Whh_f, bhh_f, Whh_b, bhh_b);
    k_gemm<<<dim3(33, 4), 256>>>(W_w, W_b, 2);
    k_embed_mem<<<16416, 256>>>(src, Ct, kb, cl);
    for (int h = 0; h < 3; h++) {
        k_logit<<<2048, 256>>>(h, out);
        k_softmax<<<32, 256>>>();
        k_okpart<<<128, 256>>>(h);
        k_okred<<<32, 256>>>();
    }
    k_proj<<<1024, 256>>>(proj_w, proj_b, out);
}